// round 3
// baseline (speedup 1.0000x reference)
#include <cuda_runtime.h>

typedef unsigned long long ull;

#define NMAX 100000
#define EMAX 3200000

// ---------------- device scratch (static, no allocation) ----------------
__device__ float g_h[(size_t)NMAX * 64];   // encoder output h
__device__ int   g_cnt[NMAX];
__device__ int   g_off[NMAX];
__device__ int   g_cur[NMAX];
__device__ int   g_edst[EMAX];
__device__ int   g_is64;

// ---------------- packed fp32x2 helpers (Blackwell FFMA2) ----------------
__device__ __forceinline__ ull fma2(ull a, ull b, ull c) {
    ull d;
    asm("fma.rn.f32x2 %0, %1, %2, %3;" : "=l"(d) : "l"(a), "l"(b), "l"(c));
    return d;
}
__device__ __forceinline__ float2 unpack2(ull v) {
    unsigned lo, hi;
    asm("mov.b64 {%0,%1}, %2;" : "=r"(lo), "=r"(hi) : "l"(v));
    return make_float2(__uint_as_float(lo), __uint_as_float(hi));
}
__device__ __forceinline__ ull splat2(float x) {
    ull d; unsigned xi = __float_as_uint(x);
    asm("mov.b64 %0, {%1, %1};" : "=l"(d) : "r"(xi));
    return d;
}

// ---------------- adj dtype detection (int64 vs int32) ----------------
__global__ void k_detect(const int* __restrict__ a) {
    if (threadIdx.x == 0 && blockIdx.x == 0) {
        int any = 0;
        #pragma unroll
        for (int i = 1; i < 128; i += 2) any |= a[i];
        g_is64 = (any == 0) ? 1 : 0;
    }
}

// ---------------- zero counts ----------------
__global__ void k_zero(int n) {
    int i = blockIdx.x * blockDim.x + threadIdx.x;
    if (i < n) g_cnt[i] = 0;
}

// ---------------- encoder: h = relu(x@W1+b1)@W2+b2, warp per node ----------------
__global__ __launch_bounds__(256) void k_enc(
    const float* __restrict__ x,
    const float* __restrict__ W1, const float* __restrict__ b1,
    const float* __restrict__ W2, const float* __restrict__ b2, int n)
{
    __shared__ float sW1[6 * 64];
    __shared__ ull   sW2[64 * 32];      // float2-packed: cols (2lane, 2lane+1)
    __shared__ float sb1[64];
    __shared__ ull   sb2[32];
    __shared__ ull   ssp[8][64];        // per-warp splatted h

    int tid = threadIdx.x;
    for (int i = tid; i < 6 * 64; i += 256) sW1[i] = W1[i];
    for (int i = tid; i < 64 * 32; i += 256) sW2[i] = ((const ull*)W2)[i];
    if (tid < 64) sb1[tid] = b1[tid];
    if (tid < 32) sb2[tid] = ((const ull*)b2)[tid];
    __syncthreads();

    int lane = tid & 31, w = tid >> 5;
    int wg = blockIdx.x * 8 + w, nw = gridDim.x * 8;
    ull* myssp = ssp[w];
    float2* hf2 = (float2*)g_h;

    for (int i = wg; i < n; i += nw) {
        float xv = (lane < 6) ? x[(size_t)i * 6 + lane] : 0.f;
        float h0 = sb1[lane], h1 = sb1[lane + 32];
        #pragma unroll
        for (int k = 0; k < 6; ++k) {
            float xk = __shfl_sync(0xffffffffu, xv, k);
            h0 = fmaf(xk, sW1[k * 64 + lane], h0);
            h1 = fmaf(xk, sW1[k * 64 + lane + 32], h1);
        }
        h0 = fmaxf(h0, 0.f); h1 = fmaxf(h1, 0.f);
        myssp[lane]      = splat2(h0);   // k = lane
        myssp[lane + 32] = splat2(h1);   // k = lane+32
        __syncwarp();
        ull acc = sb2[lane];
        #pragma unroll
        for (int k = 0; k < 64; ++k)
            acc = fma2(sW2[k * 32 + lane], myssp[k], acc);
        hf2[(size_t)i * 32 + lane] = unpack2(acc);
        __syncwarp();
    }
}

// ---------------- edge pass 1: degree counts (vectorized) ----------------
__global__ void k_count(const void* __restrict__ adj, int e) {
    long long tid = blockIdx.x * (long long)blockDim.x + threadIdx.x;
    long long stride = gridDim.x * (long long)blockDim.x;
    if (g_is64) {
        const longlong2* p = (const longlong2*)adj;
        int half = e >> 1;
        for (long long i = tid; i < half; i += stride) {
            longlong2 v = p[i];
            atomicAdd(&g_cnt[(int)v.x], 1);
            atomicAdd(&g_cnt[(int)v.y], 1);
        }
        if (tid == 0 && (e & 1))
            atomicAdd(&g_cnt[(int)((const long long*)adj)[e - 1]], 1);
    } else {
        const int4* p = (const int4*)adj;
        int q = e >> 2;
        for (long long i = tid; i < q; i += stride) {
            int4 v = p[i];
            atomicAdd(&g_cnt[v.x], 1);
            atomicAdd(&g_cnt[v.y], 1);
            atomicAdd(&g_cnt[v.z], 1);
            atomicAdd(&g_cnt[v.w], 1);
        }
        if (tid == 0)
            for (int i = q << 2; i < e; ++i)
                atomicAdd(&g_cnt[((const int*)adj)[i]], 1);
    }
}

// ---------------- exclusive scan of counts (single block) ----------------
__global__ __launch_bounds__(1024) void k_scan(int n) {
    __shared__ int s[1024];
    int t = threadIdx.x;
    int chunk = (n + 1023) / 1024;
    int beg = t * chunk, end = min(beg + chunk, n);
    int tot = 0;
    for (int i = beg; i < end; ++i) tot += g_cnt[i];
    s[t] = tot;
    __syncthreads();
    for (int d = 1; d < 1024; d <<= 1) {
        int v = (t >= d) ? s[t - d] : 0;
        __syncthreads();
        s[t] += v;
        __syncthreads();
    }
    int base = (t > 0) ? s[t - 1] : 0;
    for (int i = beg; i < end; ++i) {
        g_off[i] = base;
        g_cur[i] = base;
        base += g_cnt[i];
    }
}

// ---------------- edge pass 2: fill CSR adjacency (vectorized) ----------------
__global__ void k_fill(const void* __restrict__ adj, int e) {
    long long tid = blockIdx.x * (long long)blockDim.x + threadIdx.x;
    long long stride = gridDim.x * (long long)blockDim.x;
    if (g_is64) {
        const long long* a = (const long long*)adj;
        int half = e >> 1;
        const longlong2* ps = (const longlong2*)a;
        const longlong2* pd = (const longlong2*)(a + e);
        bool dal = ((e & 1) == 0);   // dst row longlong2-aligned?
        for (long long i = tid; i < half; i += stride) {
            longlong2 s = ps[i];
            long long d0, d1;
            if (dal) { longlong2 d = pd[i]; d0 = d.x; d1 = d.y; }
            else     { d0 = a[e + 2 * i]; d1 = a[e + 2 * i + 1]; }
            int p0 = atomicAdd(&g_cur[(int)s.x], 1);
            g_edst[p0] = (int)d0;
            int p1 = atomicAdd(&g_cur[(int)s.y], 1);
            g_edst[p1] = (int)d1;
        }
        if (tid == 0 && (e & 1)) {
            int s = (int)a[e - 1], d = (int)a[2 * e - 1];
            int p = atomicAdd(&g_cur[s], 1);
            g_edst[p] = d;
        }
    } else {
        const int* a = (const int*)adj;
        int q = e >> 2;
        bool dal = ((e & 3) == 0);
        const int4* ps = (const int4*)a;
        const int4* pd = (const int4*)(a + e);
        for (long long i = tid; i < q; i += stride) {
            int4 s = ps[i];
            int4 d;
            if (dal) d = pd[i];
            else { d.x = a[e+4*i]; d.y = a[e+4*i+1]; d.z = a[e+4*i+2]; d.w = a[e+4*i+3]; }
            int p0 = atomicAdd(&g_cur[s.x], 1); g_edst[p0] = d.x;
            int p1 = atomicAdd(&g_cur[s.y], 1); g_edst[p1] = d.y;
            int p2 = atomicAdd(&g_cur[s.z], 1); g_edst[p2] = d.z;
            int p3 = atomicAdd(&g_cur[s.w], 1); g_edst[p3] = d.w;
        }
        if (tid == 0)
            for (int i = q << 2; i < e; ++i) {
                int p = atomicAdd(&g_cur[a[i]], 1);
                g_edst[p] = a[e + i];
            }
    }
}

// ---------------- fused: aggregate + Wf1 + Wf2 + heads, warp per node ----------------
// dynamic smem layout (ull units):
//   sWf1[2048] sWf2[2048] sWh[2048] sbf1[32] sbf2[32] sbh[32]
//   sWs2+sWt2 (160 floats = 80 ull)   ssp[8][64]
#define SM_WF1 0
#define SM_WF2 2048
#define SM_WH  4096
#define SM_BF1 6144
#define SM_BF2 6176
#define SM_BH  6208
#define SM_WS2 6240           /* 32 + 128 floats = 80 ull -> ends at 6320 */
#define SM_SSP 6320
#define SM_ULLS (6320 + 8*64)
static const int FUSED_SMEM = SM_ULLS * 8;

__global__ __launch_bounds__(256) void k_fused(
    const float* __restrict__ Wf1, const float* __restrict__ bf1,
    const float* __restrict__ Wf2, const float* __restrict__ bf2,
    const float* __restrict__ Ws1, const float* __restrict__ bs1,
    const float* __restrict__ Ws2, const float* __restrict__ bs2,
    const float* __restrict__ Wt1, const float* __restrict__ bt1,
    const float* __restrict__ Wt2, const float* __restrict__ bt2,
    float* __restrict__ out, int n)
{
    extern __shared__ ull smem[];
    ull* sWf1 = smem + SM_WF1;
    ull* sWf2 = smem + SM_WF2;
    ull* sWh  = smem + SM_WH;
    ull* sbf1 = smem + SM_BF1;
    ull* sbf2 = smem + SM_BF2;
    ull* sbh  = smem + SM_BH;
    float* sWs2 = (float*)(smem + SM_WS2);       // 32 floats
    float* sWt2 = sWs2 + 32;                     // 128 floats

    int tid = threadIdx.x;
    for (int i = tid; i < 64 * 32; i += 256) {
        sWf1[i] = ((const ull*)Wf1)[i];
        sWf2[i] = ((const ull*)Wf2)[i];
    }
    // heads W: columns 0..31 = Ws1, 32..63 = Wt1, float2-packed per lane
    for (int idx = tid; idx < 64 * 64; idx += 256) {
        int k = idx >> 6, j = idx & 63;
        ((float*)sWh)[k * 64 + j] = (j < 32) ? Ws1[k * 32 + j] : Wt1[k * 32 + (j - 32)];
    }
    if (tid < 32) { sbf1[tid] = ((const ull*)bf1)[tid]; sbf2[tid] = ((const ull*)bf2)[tid]; }
    if (tid < 64) ((float*)sbh)[tid] = (tid < 32) ? bs1[tid] : bt1[tid - 32];
    if (tid < 32)  sWs2[tid] = Ws2[tid];
    if (tid < 128) sWt2[tid] = Wt2[tid];
    __syncthreads();

    int lane = tid & 31, w = tid >> 5;
    ull* myssp = smem + SM_SSP + w * 64;
    int wg = blockIdx.x * 8 + w, nw = gridDim.x * 8;
    const float2* hf2 = (const float2*)g_h;
    float bs2v = bs2[0];
    float bt20 = bt2[0], bt21 = bt2[1], bt22 = bt2[2], bt23 = bt2[3];

    for (int i = wg; i < n; i += nw) {
        int deg = g_cnt[i];
        int start = g_off[i];
        float2 sum = make_float2(0.f, 0.f);

        for (int base = 0; base < deg; base += 32) {
            int e = base + lane;
            int d = (e < deg) ? g_edst[start + e] : 0;
            int m = min(32, deg - base);
            int j = 0;
            for (; j + 4 <= m; j += 4) {
                int d0 = __shfl_sync(0xffffffffu, d, j);
                int d1 = __shfl_sync(0xffffffffu, d, j + 1);
                int d2 = __shfl_sync(0xffffffffu, d, j + 2);
                int d3 = __shfl_sync(0xffffffffu, d, j + 3);
                float2 v0 = hf2[(size_t)d0 * 32 + lane];
                float2 v1 = hf2[(size_t)d1 * 32 + lane];
                float2 v2 = hf2[(size_t)d2 * 32 + lane];
                float2 v3 = hf2[(size_t)d3 * 32 + lane];
                sum.x += (v0.x + v1.x) + (v2.x + v3.x);
                sum.y += (v0.y + v1.y) + (v2.y + v3.y);
            }
            for (; j < m; ++j) {
                int dd = __shfl_sync(0xffffffffu, d, j);
                float2 v = hf2[(size_t)dd * 32 + lane];
                sum.x += v.x; sum.y += v.y;
            }
        }

        float inv = 1.f / fmaxf((float)deg, 1.f);
        float2 hv = hf2[(size_t)i * 32 + lane];
        hv.x = fmaf(sum.x, inv, hv.x);
        hv.y = fmaf(sum.y, inv, hv.y);

        // GEMV 1: relu(h @ Wf1 + bf1)
        ((float4*)myssp)[lane] = make_float4(hv.x, hv.x, hv.y, hv.y);
        __syncwarp();
        ull acc = sbf1[lane];
        #pragma unroll
        for (int k = 0; k < 64; ++k)
            acc = fma2(sWf1[k * 32 + lane], myssp[k], acc);
        float2 o = unpack2(acc);
        o.x = fmaxf(o.x, 0.f); o.y = fmaxf(o.y, 0.f);
        __syncwarp();

        // GEMV 2: relu(o @ Wf2 + bf2)
        ((float4*)myssp)[lane] = make_float4(o.x, o.x, o.y, o.y);
        __syncwarp();
        acc = sbf2[lane];
        #pragma unroll
        for (int k = 0; k < 64; ++k)
            acc = fma2(sWf2[k * 32 + lane], myssp[k], acc);
        o = unpack2(acc);
        o.x = fmaxf(o.x, 0.f); o.y = fmaxf(o.y, 0.f);
        __syncwarp();

        // GEMV 3 (heads hidden): relu(o @ [Ws1|Wt1] + [bs1|bt1])
        ((float4*)myssp)[lane] = make_float4(o.x, o.x, o.y, o.y);
        __syncwarp();
        acc = sbh[lane];
        #pragma unroll
        for (int k = 0; k < 64; ++k)
            acc = fma2(sWh[k * 32 + lane], myssp[k], acc);
        float2 u = unpack2(acc);
        u.x = fmaxf(u.x, 0.f); u.y = fmaxf(u.y, 0.f);

        // final reductions: lanes 0..15 hold Ws1 cols, 16..31 hold Wt1 cols
        float p = 0.f, tx = 0.f, ty = 0.f, tz = 0.f, tw = 0.f;
        if (lane < 16) {
            p = u.x * sWs2[2 * lane] + u.y * sWs2[2 * lane + 1];
        } else {
            int jj = 2 * lane - 32;
            tx = fmaf(u.x, sWt2[jj * 4 + 0], u.y * sWt2[(jj + 1) * 4 + 0]);
            ty = fmaf(u.x, sWt2[jj * 4 + 1], u.y * sWt2[(jj + 1) * 4 + 1]);
            tz = fmaf(u.x, sWt2[jj * 4 + 2], u.y * sWt2[(jj + 1) * 4 + 2]);
            tw = fmaf(u.x, sWt2[jj * 4 + 3], u.y * sWt2[(jj + 1) * 4 + 3]);
        }
        #pragma unroll
        for (int o2 = 16; o2; o2 >>= 1) {
            p  += __shfl_xor_sync(0xffffffffu, p,  o2);
            tx += __shfl_xor_sync(0xffffffffu, tx, o2);
            ty += __shfl_xor_sync(0xffffffffu, ty, o2);
            tz += __shfl_xor_sync(0xffffffffu, tz, o2);
            tw += __shfl_xor_sync(0xffffffffu, tw, o2);
        }
        if (lane == 0) {
            out[i] = p + bs2v;
            float4* to = (float4*)(out + n);
            to[i] = make_float4(tx + bt20, ty + bt21, tz + bt22, tw + bt23);
        }
        __syncwarp();
    }
}

// ---------------- launch ----------------
extern "C" void kernel_launch(void* const* d_in, const int* in_sizes, int n_in,
                              void* d_out, int out_size) {
    const float* x   = (const float*)d_in[0];
    const void*  adj = d_in[1];
    const float* W1  = (const float*)d_in[2];
    const float* b1  = (const float*)d_in[3];
    const float* W2  = (const float*)d_in[4];
    const float* b2  = (const float*)d_in[5];
    const float* Wf1 = (const float*)d_in[6];
    const float* bf1 = (const float*)d_in[7];
    const float* Wf2 = (const float*)d_in[8];
    const float* bf2 = (const float*)d_in[9];
    const float* Ws1 = (const float*)d_in[10];
    const float* bs1 = (const float*)d_in[11];
    const float* Ws2 = (const float*)d_in[12];
    const float* bs2 = (const float*)d_in[13];
    const float* Wt1 = (const float*)d_in[14];
    const float* bt1 = (const float*)d_in[15];
    const float* Wt2 = (const float*)d_in[16];
    const float* bt2 = (const float*)d_in[17];

    int n = in_sizes[0] / 6;
    int e = in_sizes[1] / 2;
    float* out = (float*)d_out;

    cudaFuncSetAttribute(k_fused, cudaFuncAttributeMaxDynamicSharedMemorySize, FUSED_SMEM);

    k_detect<<<1, 32>>>((const int*)adj);
    k_zero<<<(n + 255) / 256, 256>>>(n);
    k_enc<<<1184, 256>>>(x, W1, b1, W2, b2, n);
    k_count<<<2048, 256>>>(adj, e);
    k_scan<<<1, 1024>>>(n);
    k_fill<<<2048, 256>>>(adj, e);
    k_fused<<<1184, 256, FUSED_SMEM>>>(Wf1, bf1, Wf2, bf2, Ws1, bs1, Ws2, bs2,
                                       Wt1, bt1, Wt2, bt2, out, n);
}

// round 4
// speedup vs baseline: 1.1854x; 1.1854x over previous
#include <cuda_runtime.h>
#include <cuda_fp16.h>

typedef unsigned long long ull;

#define NMAX 100000
#define EMAX 3200000

// ---------------- device scratch (static, no allocation) ----------------
__device__ float   g_h [(size_t)NMAX * 64];  // encoder output h (fp32, self term)
__device__ __half2 g_hh[(size_t)NMAX * 32];  // fp16 copy for neighbor gather
__device__ int     g_cnt[NMAX];
__device__ int     g_off[NMAX];
__device__ int     g_cur[NMAX];
__device__ int     g_edst[EMAX];
__device__ int     g_is64;

// ---------------- packed fp32x2 helpers (Blackwell FFMA2) ----------------
__device__ __forceinline__ ull fma2(ull a, ull b, ull c) {
    ull d;
    asm("fma.rn.f32x2 %0, %1, %2, %3;" : "=l"(d) : "l"(a), "l"(b), "l"(c));
    return d;
}
__device__ __forceinline__ float2 unpack2(ull v) {
    unsigned lo, hi;
    asm("mov.b64 {%0,%1}, %2;" : "=r"(lo), "=r"(hi) : "l"(v));
    return make_float2(__uint_as_float(lo), __uint_as_float(hi));
}
__device__ __forceinline__ ull splat2(float x) {
    ull d; unsigned xi = __float_as_uint(x);
    asm("mov.b64 %0, {%1, %1};" : "=l"(d) : "r"(xi));
    return d;
}

// 4-node batched GEMV (64->64): weights as quads (rows 2q,2q+1 x col-pair lane),
// activations broadcast from registers via shfl (zero smem-crossbar for acts).
__device__ __forceinline__ void gemv4_64(
    const ull* __restrict__ Wq, ull bias, int lane,
    const float2* a, float2* o)
{
    ull c0 = bias, c1 = bias, c2 = bias, c3 = bias;
    #pragma unroll
    for (int q = 0; q < 32; ++q) {
        ulonglong2 w = ((const ulonglong2*)Wq)[q * 32 + lane];
        float t;
        t = __shfl_sync(0xffffffffu, a[0].x, q); c0 = fma2(w.x, splat2(t), c0);
        t = __shfl_sync(0xffffffffu, a[0].y, q); c0 = fma2(w.y, splat2(t), c0);
        t = __shfl_sync(0xffffffffu, a[1].x, q); c1 = fma2(w.x, splat2(t), c1);
        t = __shfl_sync(0xffffffffu, a[1].y, q); c1 = fma2(w.y, splat2(t), c1);
        t = __shfl_sync(0xffffffffu, a[2].x, q); c2 = fma2(w.x, splat2(t), c2);
        t = __shfl_sync(0xffffffffu, a[2].y, q); c2 = fma2(w.y, splat2(t), c2);
        t = __shfl_sync(0xffffffffu, a[3].x, q); c3 = fma2(w.x, splat2(t), c3);
        t = __shfl_sync(0xffffffffu, a[3].y, q); c3 = fma2(w.y, splat2(t), c3);
    }
    o[0] = unpack2(c0); o[1] = unpack2(c1); o[2] = unpack2(c2); o[3] = unpack2(c3);
}

// build quad layout from row-major 64x64 W: quad(q,l) = (W[2q][2l],W[2q][2l+1],W[2q+1][2l],W[2q+1][2l+1])
__device__ __forceinline__ void build_quads(ull* dst, const float* W, int tid) {
    const ull* w = (const ull*)W;
    for (int i = tid; i < 1024; i += 256) {
        int q = i >> 5, l = i & 31;
        ulonglong2 v;
        v.x = w[(2 * q) * 32 + l];
        v.y = w[(2 * q + 1) * 32 + l];
        ((ulonglong2*)dst)[i] = v;
    }
}

// ---------------- adj dtype detection (int64 vs int32) ----------------
__global__ void k_detect(const int* __restrict__ a) {
    if (threadIdx.x == 0 && blockIdx.x == 0) {
        int any = 0;
        #pragma unroll
        for (int i = 1; i < 128; i += 2) any |= a[i];
        g_is64 = (any == 0) ? 1 : 0;
    }
}

__global__ void k_zero(int n) {
    int i = blockIdx.x * blockDim.x + threadIdx.x;
    if (i < n) g_cnt[i] = 0;
}

// ---------------- encoder: h = relu(x@W1+b1)@W2+b2, 4 nodes per warp ----------------
__global__ __launch_bounds__(256) void k_enc(
    const float* __restrict__ x,
    const float* __restrict__ W1, const float* __restrict__ b1,
    const float* __restrict__ W2, const float* __restrict__ b2, int n)
{
    __shared__ ull sW1[6 * 32];     // pair layout: (W1[k][2l], W1[k][2l+1])
    __shared__ ull sW2q[2048];      // quad layout
    __shared__ ull sb1[32];
    __shared__ ull sb2[32];

    int tid = threadIdx.x;
    for (int i = tid; i < 6 * 32; i += 256) sW1[i] = ((const ull*)W1)[i];
    build_quads(sW2q, W2, tid);
    if (tid < 32) { sb1[tid] = ((const ull*)b1)[tid]; sb2[tid] = ((const ull*)b2)[tid]; }
    __syncthreads();

    int lane = tid & 31, w = tid >> 5;
    int wg = blockIdx.x * 8 + w, nw = gridDim.x * 8;
    float2* hf2 = (float2*)g_h;

    ull w1r[6];
    #pragma unroll
    for (int k = 0; k < 6; ++k) w1r[k] = sW1[k * 32 + lane];

    for (int i0 = wg * 4; i0 < n; i0 += nw * 4) {
        // load x for 4 nodes: lane -> node (lane>>3), feature (lane&7)
        int mm = lane >> 3, f = lane & 7;
        int nodeL = min(i0 + mm, n - 1);
        float xv = (f < 6) ? x[(size_t)nodeL * 6 + f] : 0.f;

        float2 a[4];
        #pragma unroll
        for (int m = 0; m < 4; ++m) {
            ull c = sb1[lane];
            #pragma unroll
            for (int k = 0; k < 6; ++k) {
                float xk = __shfl_sync(0xffffffffu, xv, 8 * m + k);
                c = fma2(w1r[k], splat2(xk), c);
            }
            float2 t = unpack2(c);
            a[m] = make_float2(fmaxf(t.x, 0.f), fmaxf(t.y, 0.f));
        }

        float2 o[4];
        gemv4_64(sW2q, sb2[lane], lane, a, o);

        #pragma unroll
        for (int m = 0; m < 4; ++m) {
            int i = i0 + m;
            if (i < n) {
                hf2[(size_t)i * 32 + lane] = o[m];
                g_hh[(size_t)i * 32 + lane] = __float22half2_rn(o[m]);
            }
        }
    }
}

// ---------------- edge pass 1: degree counts (vectorized) ----------------
__global__ void k_count(const void* __restrict__ adj, int e) {
    long long tid = blockIdx.x * (long long)blockDim.x + threadIdx.x;
    long long stride = gridDim.x * (long long)blockDim.x;
    if (g_is64) {
        const longlong2* p = (const longlong2*)adj;
        int half = e >> 1;
        for (long long i = tid; i < half; i += stride) {
            longlong2 v = p[i];
            atomicAdd(&g_cnt[(int)v.x], 1);
            atomicAdd(&g_cnt[(int)v.y], 1);
        }
        if (tid == 0 && (e & 1))
            atomicAdd(&g_cnt[(int)((const long long*)adj)[e - 1]], 1);
    } else {
        const int4* p = (const int4*)adj;
        int q = e >> 2;
        for (long long i = tid; i < q; i += stride) {
            int4 v = p[i];
            atomicAdd(&g_cnt[v.x], 1);
            atomicAdd(&g_cnt[v.y], 1);
            atomicAdd(&g_cnt[v.z], 1);
            atomicAdd(&g_cnt[v.w], 1);
        }
        if (tid == 0)
            for (int i = q << 2; i < e; ++i)
                atomicAdd(&g_cnt[((const int*)adj)[i]], 1);
    }
}

// ---------------- exclusive scan of counts (single block) ----------------
__global__ __launch_bounds__(1024) void k_scan(int n) {
    __shared__ int s[1024];
    int t = threadIdx.x;
    int chunk = (n + 1023) / 1024;
    int beg = t * chunk, end = min(beg + chunk, n);
    int tot = 0;
    for (int i = beg; i < end; ++i) tot += g_cnt[i];
    s[t] = tot;
    __syncthreads();
    for (int d = 1; d < 1024; d <<= 1) {
        int v = (t >= d) ? s[t - d] : 0;
        __syncthreads();
        s[t] += v;
        __syncthreads();
    }
    int base = (t > 0) ? s[t - 1] : 0;
    for (int i = beg; i < end; ++i) {
        g_off[i] = base;
        g_cur[i] = base;
        base += g_cnt[i];
    }
}

// ---------------- edge pass 2: fill CSR adjacency (vectorized) ----------------
__global__ void k_fill(const void* __restrict__ adj, int e) {
    long long tid = blockIdx.x * (long long)blockDim.x + threadIdx.x;
    long long stride = gridDim.x * (long long)blockDim.x;
    if (g_is64) {
        const long long* a = (const long long*)adj;
        int half = e >> 1;
        const longlong2* ps = (const longlong2*)a;
        const longlong2* pd = (const longlong2*)(a + e);
        bool dal = ((e & 1) == 0);
        for (long long i = tid; i < half; i += stride) {
            longlong2 s = ps[i];
            long long d0, d1;
            if (dal) { longlong2 d = pd[i]; d0 = d.x; d1 = d.y; }
            else     { d0 = a[e + 2 * i]; d1 = a[e + 2 * i + 1]; }
            int p0 = atomicAdd(&g_cur[(int)s.x], 1);
            g_edst[p0] = (int)d0;
            int p1 = atomicAdd(&g_cur[(int)s.y], 1);
            g_edst[p1] = (int)d1;
        }
        if (tid == 0 && (e & 1)) {
            int s = (int)a[e - 1], d = (int)a[2 * e - 1];
            int p = atomicAdd(&g_cur[s], 1);
            g_edst[p] = d;
        }
    } else {
        const int* a = (const int*)adj;
        int q = e >> 2;
        bool dal = ((e & 3) == 0);
        const int4* ps = (const int4*)a;
        const int4* pd = (const int4*)(a + e);
        for (long long i = tid; i < q; i += stride) {
            int4 s = ps[i];
            int4 d;
            if (dal) d = pd[i];
            else { d.x = a[e+4*i]; d.y = a[e+4*i+1]; d.z = a[e+4*i+2]; d.w = a[e+4*i+3]; }
            int p0 = atomicAdd(&g_cur[s.x], 1); g_edst[p0] = d.x;
            int p1 = atomicAdd(&g_cur[s.y], 1); g_edst[p1] = d.y;
            int p2 = atomicAdd(&g_cur[s.z], 1); g_edst[p2] = d.z;
            int p3 = atomicAdd(&g_cur[s.w], 1); g_edst[p3] = d.w;
        }
        if (tid == 0)
            for (int i = q << 2; i < e; ++i) {
                int p = atomicAdd(&g_cur[a[i]], 1);
                g_edst[p] = a[e + i];
            }
    }
}

// ---------------- fused: aggregate + Wf1 + Wf2 + heads, 4 nodes per warp ----------------
// dynamic smem (ull units): quads Wf1[2048] Wf2[2048] Wh[2048], sbf1[32] sbf2[32] sbh[32],
// sWs2+sWt2 (160 floats = 80 ull)
#define SM_WF1 0
#define SM_WF2 2048
#define SM_WH  4096
#define SM_BF1 6144
#define SM_BF2 6176
#define SM_BH  6208
#define SM_WS2 6240
#define SM_ULLS 6320
static const int FUSED_SMEM = SM_ULLS * 8;

__global__ __launch_bounds__(256) void k_fused(
    const float* __restrict__ Wf1, const float* __restrict__ bf1,
    const float* __restrict__ Wf2, const float* __restrict__ bf2,
    const float* __restrict__ Ws1, const float* __restrict__ bs1,
    const float* __restrict__ Ws2, const float* __restrict__ bs2,
    const float* __restrict__ Wt1, const float* __restrict__ bt1,
    const float* __restrict__ Wt2, const float* __restrict__ bt2,
    float* __restrict__ out, int n)
{
    extern __shared__ ull smem[];
    ull* sWf1 = smem + SM_WF1;
    ull* sWf2 = smem + SM_WF2;
    ull* sWh  = smem + SM_WH;
    ull* sbf1 = smem + SM_BF1;
    ull* sbf2 = smem + SM_BF2;
    ull* sbh  = smem + SM_BH;
    float* sWs2 = (float*)(smem + SM_WS2);  // 32 floats
    float* sWt2 = sWs2 + 32;                // 128 floats

    int tid = threadIdx.x;
    build_quads(sWf1, Wf1, tid);
    build_quads(sWf2, Wf2, tid);
    // heads combined [Ws1|Wt1] quads: j = 2l,2l+1 (l<16 -> Ws1, else Wt1)
    for (int i = tid; i < 1024; i += 256) {
        int q = i >> 5, l = i & 31;
        const float* src = (l < 16) ? Ws1 : Wt1;
        int jj = (l < 16) ? 2 * l : 2 * l - 32;
        float4 f;
        f.x = src[(2 * q) * 32 + jj];
        f.y = src[(2 * q) * 32 + jj + 1];
        f.z = src[(2 * q + 1) * 32 + jj];
        f.w = src[(2 * q + 1) * 32 + jj + 1];
        ((float4*)sWh)[i] = f;
    }
    if (tid < 32) { sbf1[tid] = ((const ull*)bf1)[tid]; sbf2[tid] = ((const ull*)bf2)[tid]; }
    if (tid < 64) ((float*)sbh)[tid] = (tid < 32) ? bs1[tid] : bt1[tid - 32];
    if (tid < 32)  sWs2[tid] = Ws2[tid];
    if (tid < 128) sWt2[tid] = Wt2[tid];
    __syncthreads();

    int lane = tid & 31, w = tid >> 5;
    int wg = blockIdx.x * 8 + w, nw = gridDim.x * 8;
    const float2* hf2 = (const float2*)g_h;
    const __half2* hh = g_hh;
    float bs2v = bs2[0];
    float bt20 = bt2[0], bt21 = bt2[1], bt22 = bt2[2], bt23 = bt2[3];

    for (int i0 = wg * 4; i0 < n; i0 += nw * 4) {
        float2 hv[4];
        #pragma unroll
        for (int m = 0; m < 4; ++m) {
            int i = min(i0 + m, n - 1);
            int deg = g_cnt[i];
            int start = g_off[i];
            float2 sum = make_float2(0.f, 0.f);

            for (int base = 0; base < deg; base += 32) {
                int e = base + lane;
                int d = (e < deg) ? g_edst[start + e] : 0;
                int cnt = min(32, deg - base);
                int j = 0;
                for (; j + 4 <= cnt; j += 4) {
                    int d0 = __shfl_sync(0xffffffffu, d, j);
                    int d1 = __shfl_sync(0xffffffffu, d, j + 1);
                    int d2 = __shfl_sync(0xffffffffu, d, j + 2);
                    int d3 = __shfl_sync(0xffffffffu, d, j + 3);
                    float2 v0 = __half22float2(hh[(size_t)d0 * 32 + lane]);
                    float2 v1 = __half22float2(hh[(size_t)d1 * 32 + lane]);
                    float2 v2 = __half22float2(hh[(size_t)d2 * 32 + lane]);
                    float2 v3 = __half22float2(hh[(size_t)d3 * 32 + lane]);
                    sum.x += (v0.x + v1.x) + (v2.x + v3.x);
                    sum.y += (v0.y + v1.y) + (v2.y + v3.y);
                }
                for (; j < cnt; ++j) {
                    int dd = __shfl_sync(0xffffffffu, d, j);
                    float2 v = __half22float2(hh[(size_t)dd * 32 + lane]);
                    sum.x += v.x; sum.y += v.y;
                }
            }

            float inv = 1.f / fmaxf((float)deg, 1.f);
            float2 self = hf2[(size_t)i * 32 + lane];
            hv[m].x = fmaf(sum.x, inv, self.x);
            hv[m].y = fmaf(sum.y, inv, self.y);
        }

        // GEMV 1: relu(h @ Wf1 + bf1)
        float2 o1[4];
        gemv4_64(sWf1, sbf1[lane], lane, hv, o1);
        #pragma unroll
        for (int m = 0; m < 4; ++m) {
            o1[m].x = fmaxf(o1[m].x, 0.f); o1[m].y = fmaxf(o1[m].y, 0.f);
        }

        // GEMV 2: relu(o1 @ Wf2 + bf2)
        float2 o2[4];
        gemv4_64(sWf2, sbf2[lane], lane, o1, o2);
        #pragma unroll
        for (int m = 0; m < 4; ++m) {
            o2[m].x = fmaxf(o2[m].x, 0.f); o2[m].y = fmaxf(o2[m].y, 0.f);
        }

        // GEMV 3: relu(o2 @ [Ws1|Wt1] + [bs1|bt1])
        float2 u[4];
        gemv4_64(sWh, sbh[lane], lane, o2, u);

        #pragma unroll
        for (int m = 0; m < 4; ++m) {
            float ux = fmaxf(u[m].x, 0.f), uy = fmaxf(u[m].y, 0.f);
            float p = 0.f, tx = 0.f, ty = 0.f, tz = 0.f, tw = 0.f;
            if (lane < 16) {
                p = ux * sWs2[2 * lane] + uy * sWs2[2 * lane + 1];
            } else {
                int jj = 2 * lane - 32;
                tx = fmaf(ux, sWt2[jj * 4 + 0], uy * sWt2[(jj + 1) * 4 + 0]);
                ty = fmaf(ux, sWt2[jj * 4 + 1], uy * sWt2[(jj + 1) * 4 + 1]);
                tz = fmaf(ux, sWt2[jj * 4 + 2], uy * sWt2[(jj + 1) * 4 + 2]);
                tw = fmaf(ux, sWt2[jj * 4 + 3], uy * sWt2[(jj + 1) * 4 + 3]);
            }
            #pragma unroll
            for (int s = 16; s; s >>= 1) {
                p  += __shfl_xor_sync(0xffffffffu, p,  s);
                tx += __shfl_xor_sync(0xffffffffu, tx, s);
                ty += __shfl_xor_sync(0xffffffffu, ty, s);
                tz += __shfl_xor_sync(0xffffffffu, tz, s);
                tw += __shfl_xor_sync(0xffffffffu, tw, s);
            }
            if (lane == 0 && i0 + m < n) {
                int i = i0 + m;
                out[i] = p + bs2v;
                float4* to = (float4*)(out + n);
                to[i] = make_float4(tx + bt20, ty + bt21, tz + bt22, tw + bt23);
            }
        }
    }
}

// ---------------- launch ----------------
extern "C" void kernel_launch(void* const* d_in, const int* in_sizes, int n_in,
                              void* d_out, int out_size) {
    const float* x   = (const float*)d_in[0];
    const void*  adj = d_in[1];
    const float* W1  = (const float*)d_in[2];
    const float* b1  = (const float*)d_in[3];
    const float* W2  = (const float*)d_in[4];
    const float* b2  = (const float*)d_in[5];
    const float* Wf1 = (const float*)d_in[6];
    const float* bf1 = (const float*)d_in[7];
    const float* Wf2 = (const float*)d_in[8];
    const float* bf2 = (const float*)d_in[9];
    const float* Ws1 = (const float*)d_in[10];
    const float* bs1 = (const float*)d_in[11];
    const float* Ws2 = (const float*)d_in[12];
    const float* bs2 = (const float*)d_in[13];
    const float* Wt1 = (const float*)d_in[14];
    const float* bt1 = (const float*)d_in[15];
    const float* Wt2 = (const float*)d_in[16];
    const float* bt2 = (const float*)d_in[17];

    int n = in_sizes[0] / 6;
    int e = in_sizes[1] / 2;
    float* out = (float*)d_out;

    cudaFuncSetAttribute(k_fused, cudaFuncAttributeMaxDynamicSharedMemorySize, FUSED_SMEM);

    k_detect<<<1, 32>>>((const int*)adj);
    k_zero<<<(n + 255) / 256, 256>>>(n);
    k_enc<<<1184, 256>>>(x, W1, b1, W2, b2, n);
    k_count<<<2048, 256>>>(adj, e);
    k_scan<<<1, 1024>>>(n);
    k_fill<<<2048, 256>>>(adj, e);
    k_fused<<<592, 256, FUSED_SMEM>>>(Wf1, bf1, Wf2, bf2, Ws1, bs1, Ws2, bs2,
                                      Wt1, bt1, Wt2, bt2, out, n);
}

// round 5
// speedup vs baseline: 1.3083x; 1.1037x over previous
#include <cuda_runtime.h>
#include <cuda_fp16.h>

typedef unsigned long long ull;

#define NMAX 100000
#define EMAX 3200000

// ---------------- device scratch (zero-initialized at load) ----------------
// Feature layout everywhere: lane-slot l holds features (l, l+32).
__device__ float2  g_h [(size_t)NMAX * 32];  // fp32 (h[l], h[l+32]) for self term
__device__ __half2 g_hh[(size_t)NMAX * 32];  // fp16 copy for neighbor gather
__device__ int     g_cnt[NMAX];              // zero at load; scan re-zeroes each call
__device__ int     g_off[NMAX];
__device__ int     g_cur[NMAX];              // after fill: cur[i] = off[i] + deg[i]
__device__ int     g_edst[EMAX];

// ---------------- packed fp32x2 helpers ----------------
__device__ __forceinline__ ull fma2(ull a, ull b, ull c) {
    ull d;
    asm("fma.rn.f32x2 %0, %1, %2, %3;" : "=l"(d) : "l"(a), "l"(b), "l"(c));
    return d;
}
__device__ __forceinline__ float2 unpack2(ull v) {
    unsigned lo, hi;
    asm("mov.b64 {%0,%1}, %2;" : "=r"(lo), "=r"(hi) : "l"(v));
    return make_float2(__uint_as_float(lo), __uint_as_float(hi));
}

// adj dtype: if int64 (values < 1e5), odd 32-bit words are all zero.
__device__ __forceinline__ int detect64(const int* __restrict__ a) {
    int any = 0;
    #pragma unroll
    for (int i = 1; i < 32; i += 2) any |= a[i];
    return any == 0;
}

// quad layout (k-major): quad[q*32+l] = (W[2q][l], W[2q+1][l], W[2q][l+32], W[2q+1][l+32])
__device__ __forceinline__ void build_quads64(float4* dst, const float* __restrict__ W, int tid) {
    for (int i = tid; i < 1024; i += 256) {
        int q = i >> 5, l = i & 31;
        float4 f;
        f.x = W[(2 * q) * 64 + l];
        f.y = W[(2 * q + 1) * 64 + l];
        f.z = W[(2 * q) * 64 + l + 32];
        f.w = W[(2 * q + 1) * 64 + l + 32];
        dst[i] = f;
    }
}

// 2-node k-major GEMV 64->64. acts: 64 scalars per node in smem (index = k).
// Output: o.x = column l, o.y = column l+32 (pre-bias).
__device__ __forceinline__ void gemv2k(
    const ulonglong2* __restrict__ Wq,
    const float* __restrict__ a0, const float* __restrict__ a1,
    int lane, float2& o0, float2& o1)
{
    ull c0l = 0, c0h = 0, c1l = 0, c1h = 0;
    #pragma unroll
    for (int q = 0; q < 32; ++q) {
        ulonglong2 w = Wq[q * 32 + lane];
        ull a = *(const ull*)(a0 + 2 * q);
        ull b = *(const ull*)(a1 + 2 * q);
        c0l = fma2(w.x, a, c0l); c0h = fma2(w.y, a, c0h);
        c1l = fma2(w.x, b, c1l); c1h = fma2(w.y, b, c1h);
    }
    float2 t;
    t = unpack2(c0l); o0.x = t.x + t.y;
    t = unpack2(c0h); o0.y = t.x + t.y;
    t = unpack2(c1l); o1.x = t.x + t.y;
    t = unpack2(c1h); o1.y = t.x + t.y;
}

// ============ kernel 1: encoder MLP (2 nodes/warp) + edge degree count ============
__global__ __launch_bounds__(256) void k_enc_count(
    const float* __restrict__ x,
    const float* __restrict__ W1, const float* __restrict__ b1,
    const float* __restrict__ W2, const float* __restrict__ b2,
    const void* __restrict__ adj, int n, int e)
{
    __shared__ float4 sW1q[3 * 32];          // 6 input rows -> 3 k-pairs
    __shared__ float4 sW2q[1024];
    __shared__ float  sx[8][2][8];           // x features, padded to 8
    __shared__ float  sact[8][2][64];

    int tid = threadIdx.x;
    for (int i = tid; i < 3 * 32; i += 256) {
        int q = i >> 5, l = i & 31;
        float4 f;
        f.x = W1[(2 * q) * 64 + l];
        f.y = W1[(2 * q + 1) * 64 + l];
        f.z = W1[(2 * q) * 64 + l + 32];
        f.w = W1[(2 * q + 1) * 64 + l + 32];
        sW1q[i] = f;
    }
    build_quads64(sW2q, W2, tid);
    __syncthreads();

    int lane = tid & 31, w = tid >> 5;
    float b1l = b1[lane], b1h = b1[lane + 32];
    float b2l = b2[lane], b2h = b2[lane + 32];

    int wg = blockIdx.x * 8 + w, nw = gridDim.x * 8;

    for (int i0 = wg * 2; i0 < n; i0 += nw * 2) {
        // stage x for 2 nodes
        if (lane < 12) {
            int m = lane / 6, f = lane % 6;
            int node = min(i0 + m, n - 1);
            sx[w][m][f] = x[(size_t)node * 6 + f];
        }
        __syncwarp();

        // GEMV1: 6 -> 64
        float2 a0, a1;
        {
            ull c0l = 0, c0h = 0, c1l = 0, c1h = 0;
            #pragma unroll
            for (int q = 0; q < 3; ++q) {
                ulonglong2 wq = ((const ulonglong2*)sW1q)[q * 32 + lane];
                ull a = *(const ull*)(&sx[w][0][2 * q]);
                ull b = *(const ull*)(&sx[w][1][2 * q]);
                c0l = fma2(wq.x, a, c0l); c0h = fma2(wq.y, a, c0h);
                c1l = fma2(wq.x, b, c1l); c1h = fma2(wq.y, b, c1h);
            }
            float2 t;
            t = unpack2(c0l); a0.x = fmaxf(t.x + t.y + b1l, 0.f);
            t = unpack2(c0h); a0.y = fmaxf(t.x + t.y + b1h, 0.f);
            t = unpack2(c1l); a1.x = fmaxf(t.x + t.y + b1l, 0.f);
            t = unpack2(c1h); a1.y = fmaxf(t.x + t.y + b1h, 0.f);
        }
        sact[w][0][lane] = a0.x; sact[w][0][lane + 32] = a0.y;
        sact[w][1][lane] = a1.x; sact[w][1][lane + 32] = a1.y;
        __syncwarp();

        // GEMV2: 64 -> 64
        float2 o0, o1;
        gemv2k((const ulonglong2*)sW2q, sact[w][0], sact[w][1], lane, o0, o1);
        o0.x += b2l; o0.y += b2h; o1.x += b2l; o1.y += b2h;

        if (i0 < n) {
            g_h [(size_t)i0 * 32 + lane] = o0;
            g_hh[(size_t)i0 * 32 + lane] = __float22half2_rn(o0);
        }
        if (i0 + 1 < n) {
            g_h [(size_t)(i0 + 1) * 32 + lane] = o1;
            g_hh[(size_t)(i0 + 1) * 32 + lane] = __float22half2_rn(o1);
        }
        __syncwarp();
    }

    // ---- edge degree count (overlaps with other blocks' MLP work) ----
    int is64 = detect64((const int*)adj);
    long long t = blockIdx.x * (long long)blockDim.x + threadIdx.x;
    long long stride = gridDim.x * (long long)blockDim.x;
    if (is64) {
        const longlong2* p = (const longlong2*)adj;
        int half = e >> 1;
        for (long long i = t; i < half; i += stride) {
            longlong2 v = p[i];
            atomicAdd(&g_cnt[(int)v.x], 1);
            atomicAdd(&g_cnt[(int)v.y], 1);
        }
        if (t == 0 && (e & 1))
            atomicAdd(&g_cnt[(int)((const long long*)adj)[e - 1]], 1);
    } else {
        const int4* p = (const int4*)adj;
        int q = e >> 2;
        for (long long i = t; i < q; i += stride) {
            int4 v = p[i];
            atomicAdd(&g_cnt[v.x], 1);
            atomicAdd(&g_cnt[v.y], 1);
            atomicAdd(&g_cnt[v.z], 1);
            atomicAdd(&g_cnt[v.w], 1);
        }
        if (t == 0)
            for (int i = q << 2; i < e; ++i)
                atomicAdd(&g_cnt[((const int*)adj)[i]], 1);
    }
}

// ============ kernel 2: exclusive scan (single block) + zero counts ============
__global__ __launch_bounds__(1024) void k_scan(int n) {
    __shared__ int s[1024];
    int t = threadIdx.x;
    int chunk = (n + 1023) / 1024;
    int beg = t * chunk, end = min(beg + chunk, n);
    int tot = 0;
    for (int i = beg; i < end; ++i) tot += g_cnt[i];
    s[t] = tot;
    __syncthreads();
    for (int d = 1; d < 1024; d <<= 1) {
        int v = (t >= d) ? s[t - d] : 0;
        __syncthreads();
        s[t] += v;
        __syncthreads();
    }
    int base = (t > 0) ? s[t - 1] : 0;
    for (int i = beg; i < end; ++i) {
        int c = g_cnt[i];
        g_cnt[i] = 0;              // reset for next graph replay
        g_off[i] = base;
        g_cur[i] = base;
        base += c;
    }
}

// ============ kernel 3: fill CSR adjacency ============
__global__ void k_fill(const void* __restrict__ adj, int e) {
    int is64 = detect64((const int*)adj);
    long long tid = blockIdx.x * (long long)blockDim.x + threadIdx.x;
    long long stride = gridDim.x * (long long)blockDim.x;
    if (is64) {
        const long long* a = (const long long*)adj;
        int half = e >> 1;
        const longlong2* ps = (const longlong2*)a;
        const longlong2* pd = (const longlong2*)(a + e);
        bool dal = ((e & 1) == 0);
        for (long long i = tid; i < half; i += stride) {
            longlong2 s = ps[i];
            long long d0, d1;
            if (dal) { longlong2 d = pd[i]; d0 = d.x; d1 = d.y; }
            else     { d0 = a[e + 2 * i]; d1 = a[e + 2 * i + 1]; }
            int p0 = atomicAdd(&g_cur[(int)s.x], 1);
            g_edst[p0] = (int)d0;
            int p1 = atomicAdd(&g_cur[(int)s.y], 1);
            g_edst[p1] = (int)d1;
        }
        if (tid == 0 && (e & 1)) {
            int s = (int)a[e - 1], d = (int)a[2 * e - 1];
            int p = atomicAdd(&g_cur[s], 1);
            g_edst[p] = d;
        }
    } else {
        const int* a = (const int*)adj;
        int q = e >> 2;
        bool dal = ((e & 3) == 0);
        const int4* ps = (const int4*)a;
        const int4* pd = (const int4*)(a + e);
        for (long long i = tid; i < q; i += stride) {
            int4 s = ps[i];
            int4 d;
            if (dal) d = pd[i];
            else { d.x = a[e+4*i]; d.y = a[e+4*i+1]; d.z = a[e+4*i+2]; d.w = a[e+4*i+3]; }
            int p0 = atomicAdd(&g_cur[s.x], 1); g_edst[p0] = d.x;
            int p1 = atomicAdd(&g_cur[s.y], 1); g_edst[p1] = d.y;
            int p2 = atomicAdd(&g_cur[s.z], 1); g_edst[p2] = d.z;
            int p3 = atomicAdd(&g_cur[s.w], 1); g_edst[p3] = d.w;
        }
        if (tid == 0)
            for (int i = q << 2; i < e; ++i) {
                int p = atomicAdd(&g_cur[a[i]], 1);
                g_edst[p] = a[e + i];
            }
    }
}

// ============ kernel 4: fused aggregate + Wf1 + Wf2 + heads (2 nodes/warp) ============
// dynamic smem: Wf1 quads [16KB] Wf2 quads [16KB] Wh quads [16KB] acts [8][2][64] f32 [4KB]
#define FQ_WF1 0
#define FQ_WF2 1024
#define FQ_WH  2048
#define FQ_ACT 3072      /* float4 index; acts viewed as floats from here */
static const int FUSED_SMEM = (3072 + 8 * 2 * 16) * 16;   // 53248 B

__global__ __launch_bounds__(256, 4) void k_fused(
    const float* __restrict__ Wf1, const float* __restrict__ bf1,
    const float* __restrict__ Wf2, const float* __restrict__ bf2,
    const float* __restrict__ Ws1, const float* __restrict__ bs1,
    const float* __restrict__ Ws2, const float* __restrict__ bs2,
    const float* __restrict__ Wt1, const float* __restrict__ bt1,
    const float* __restrict__ Wt2, const float* __restrict__ bt2,
    float* __restrict__ out, int n)
{
    extern __shared__ float4 smem4[];
    float4* sWf1 = smem4 + FQ_WF1;
    float4* sWf2 = smem4 + FQ_WF2;
    float4* sWh  = smem4 + FQ_WH;
    float*  sactbase = (float*)(smem4 + FQ_ACT);

    int tid = threadIdx.x;
    build_quads64(sWf1, Wf1, tid);
    build_quads64(sWf2, Wf2, tid);
    // Wh quad: lo pair = Ws1 col l (k-pair), hi pair = Wt1 col l
    for (int i = tid; i < 1024; i += 256) {
        int q = i >> 5, l = i & 31;
        float4 f;
        f.x = Ws1[(2 * q) * 32 + l];
        f.y = Ws1[(2 * q + 1) * 32 + l];
        f.z = Wt1[(2 * q) * 32 + l];
        f.w = Wt1[(2 * q + 1) * 32 + l];
        sWh[i] = f;
    }
    __syncthreads();

    int lane = tid & 31, w = tid >> 5;
    float* act0 = sactbase + (w * 2 + 0) * 64;
    float* act1 = sactbase + (w * 2 + 1) * 64;

    // per-lane constants in registers
    float bf1l = bf1[lane], bf1h = bf1[lane + 32];
    float bf2l = bf2[lane], bf2h = bf2[lane + 32];
    float bs1v = bs1[lane], bt1v = bt1[lane];
    float ws2v = Ws2[lane];
    float4 wt2v = ((const float4*)Wt2)[lane];
    float bs2v = bs2[0];
    float4 bt2v = ((const float4*)bt2)[0];

    int wg = blockIdx.x * 8 + w, nw = gridDim.x * 8;
    const __half2* hh = g_hh;
    float4* tout = (float4*)(out + n);

    for (int i0 = wg * 2; i0 < n; i0 += nw * 2) {
        float2 hv[2];
        #pragma unroll
        for (int m = 0; m < 2; ++m) {
            int i = min(i0 + m, n - 1);
            int start = g_off[i];
            int deg = g_cur[i] - start;
            __half2 s0 = __float2half2_rn(0.f), s1 = __float2half2_rn(0.f);

            for (int base = 0; base < deg; base += 32) {
                int e = base + lane;
                int d = (e < deg) ? g_edst[start + e] : 0;
                int cnt = min(32, deg - base);
                int j = 0;
                for (; j + 4 <= cnt; j += 4) {
                    int d0 = __shfl_sync(0xffffffffu, d, j);
                    int d1 = __shfl_sync(0xffffffffu, d, j + 1);
                    int d2 = __shfl_sync(0xffffffffu, d, j + 2);
                    int d3 = __shfl_sync(0xffffffffu, d, j + 3);
                    __half2 v0 = hh[(size_t)d0 * 32 + lane];
                    __half2 v1 = hh[(size_t)d1 * 32 + lane];
                    __half2 v2 = hh[(size_t)d2 * 32 + lane];
                    __half2 v3 = hh[(size_t)d3 * 32 + lane];
                    s0 = __hadd2(s0, v0); s1 = __hadd2(s1, v1);
                    s0 = __hadd2(s0, v2); s1 = __hadd2(s1, v3);
                }
                for (; j < cnt; ++j) {
                    int dd = __shfl_sync(0xffffffffu, d, j);
                    s0 = __hadd2(s0, hh[(size_t)dd * 32 + lane]);
                }
            }
            float2 f0 = __half22float2(s0), f1 = __half22float2(s1);
            float2 sum = make_float2(f0.x + f1.x, f0.y + f1.y);
            float inv = 1.f / fmaxf((float)deg, 1.f);
            float2 self = g_h[(size_t)i * 32 + lane];
            hv[m].x = fmaf(sum.x, inv, self.x);
            hv[m].y = fmaf(sum.y, inv, self.y);
        }

        // stage acts (feature index = k layout)
        act0[lane] = hv[0].x; act0[lane + 32] = hv[0].y;
        act1[lane] = hv[1].x; act1[lane + 32] = hv[1].y;
        __syncwarp();

        // GEMV 1
        float2 o0, o1;
        gemv2k((const ulonglong2*)sWf1, act0, act1, lane, o0, o1);
        o0.x = fmaxf(o0.x + bf1l, 0.f); o0.y = fmaxf(o0.y + bf1h, 0.f);
        o1.x = fmaxf(o1.x + bf1l, 0.f); o1.y = fmaxf(o1.y + bf1h, 0.f);
        __syncwarp();
        act0[lane] = o0.x; act0[lane + 32] = o0.y;
        act1[lane] = o1.x; act1[lane + 32] = o1.y;
        __syncwarp();

        // GEMV 2
        gemv2k((const ulonglong2*)sWf2, act0, act1, lane, o0, o1);
        o0.x = fmaxf(o0.x + bf2l, 0.f); o0.y = fmaxf(o0.y + bf2h, 0.f);
        o1.x = fmaxf(o1.x + bf2l, 0.f); o1.y = fmaxf(o1.y + bf2h, 0.f);
        __syncwarp();
        act0[lane] = o0.x; act0[lane + 32] = o0.y;
        act1[lane] = o1.x; act1[lane + 32] = o1.y;
        __syncwarp();

        // GEMV 3: lo = scores hidden (col lane), hi = types hidden (col lane)
        float2 u0, u1;
        gemv2k((const ulonglong2*)sWh, act0, act1, lane, u0, u1);

        #pragma unroll
        for (int m = 0; m < 2; ++m) {
            float2 u = m ? u1 : u0;
            float us = fmaxf(u.x + bs1v, 0.f);
            float ut = fmaxf(u.y + bt1v, 0.f);
            float p  = us * ws2v;
            float tx = ut * wt2v.x, ty = ut * wt2v.y, tz = ut * wt2v.z, tw = ut * wt2v.w;
            #pragma unroll
            for (int s = 16; s; s >>= 1) {
                p  += __shfl_xor_sync(0xffffffffu, p,  s);
                tx += __shfl_xor_sync(0xffffffffu, tx, s);
                ty += __shfl_xor_sync(0xffffffffu, ty, s);
                tz += __shfl_xor_sync(0xffffffffu, tz, s);
                tw += __shfl_xor_sync(0xffffffffu, tw, s);
            }
            int i = i0 + m;
            if (lane == 0 && i < n) {
                out[i] = p + bs2v;
                tout[i] = make_float4(tx + bt2v.x, ty + bt2v.y, tz + bt2v.z, tw + bt2v.w);
            }
        }
        __syncwarp();
    }
}

// ---------------- launch ----------------
extern "C" void kernel_launch(void* const* d_in, const int* in_sizes, int n_in,
                              void* d_out, int out_size) {
    const float* x   = (const float*)d_in[0];
    const void*  adj = d_in[1];
    const float* W1  = (const float*)d_in[2];
    const float* b1  = (const float*)d_in[3];
    const float* W2  = (const float*)d_in[4];
    const float* b2  = (const float*)d_in[5];
    const float* Wf1 = (const float*)d_in[6];
    const float* bf1 = (const float*)d_in[7];
    const float* Wf2 = (const float*)d_in[8];
    const float* bf2 = (const float*)d_in[9];
    const float* Ws1 = (const float*)d_in[10];
    const float* bs1 = (const float*)d_in[11];
    const float* Ws2 = (const float*)d_in[12];
    const float* bs2 = (const float*)d_in[13];
    const float* Wt1 = (const float*)d_in[14];
    const float* bt1 = (const float*)d_in[15];
    const float* Wt2 = (const float*)d_in[16];
    const float* bt2 = (const float*)d_in[17];

    int n = in_sizes[0] / 6;
    int e = in_sizes[1] / 2;
    float* out = (float*)d_out;

    cudaFuncSetAttribute(k_fused, cudaFuncAttributeMaxDynamicSharedMemorySize, FUSED_SMEM);

    k_enc_count<<<1184, 256>>>(x, W1, b1, W2, b2, adj, n, e);
    k_scan<<<1, 1024>>>(n);
    k_fill<<<2048, 256>>>(adj, e);
    k_fused<<<592, 256, FUSED_SMEM>>>(Wf1, bf1, Wf2, bf2, Ws1, bs1, Ws2, bs2,
                                      Wt1, bt1, Wt2, bt2, out, n);
}